// round 14
// baseline (speedup 1.0000x reference)
#include <cuda_runtime.h>
#include <cuda_bf16.h>
#include <cstdint>

// y[M,N] = x[M,K] @ W[N,K]^T + bias[N].  M=8192, N=K=3072.
// GROUND TRUTH (probe-decoded R13): ALL buffers are f32 containers.
//   x    : f32 of bf16-exact values  [M*K]
//   W    : f32 of e4m3-exact values  [N*K], row-major [N][K]
//   bias : f32 (bf16-exact values; runtime fallback to bf16 container)
//   out  : f32; reference = bf16(bf16(x@W^T) + bias), so replicate the
//          double bf16 rounding and store as f32.
// Engine: validated R3/R6 HMMA pipeline (mma.sync bf16, explicit fragments),
// W pre-converted once to bf16 scratch (halves B traffic), A converted
// f32->bf16 on the smem-fill path.

#define MTOT 8192
#define NTOT 3072
#define KTOT 3072

#define TILE_M 128
#define TILE_N 256
#define KC 64
#define NCHUNK (KTOT / KC)       // 48
#define NTHREADS 512

#define STRIDE 144               // smem row stride bytes (128B data + 16B pad)
#define A_BYTES (TILE_M * STRIDE)            // 18432
#define B_BYTES (TILE_N * STRIDE)            // 36864
#define STAGE_BYTES (A_BYTES + B_BYTES)      // 55296
#define SMEM_BYTES (2 * STAGE_BYTES)         // 110592

// bf16 weight scratch (allocation-free rule: __device__ global)
__device__ __align__(16) __nv_bfloat16 g_wb[(size_t)NTOT * KTOT];

// ---------------------------------------------------------------------------
__device__ __forceinline__ uint32_t smem_u32(const void* p) {
    uint32_t a;
    asm("{ .reg .u64 t; cvta.to.shared.u64 t, %1; cvt.u32.u64 %0, t; }"
        : "=r"(a) : "l"(p));
    return a;
}
__device__ __forceinline__ void cp_async16(uint32_t saddr, const void* gaddr) {
    asm volatile("cp.async.cg.shared.global [%0], [%1], 16;"
                 :: "r"(saddr), "l"(gaddr));
}
__device__ __forceinline__ uint32_t lds32(uint32_t addr) {
    uint32_t v;
    asm volatile("ld.shared.b32 %0, [%1];" : "=r"(v) : "r"(addr));
    return v;
}
__device__ __forceinline__ void mma_bf16(float (&c)[4], const uint32_t (&a)[4],
                                         uint32_t b0, uint32_t b1) {
    asm volatile(
        "mma.sync.aligned.m16n8k16.row.col.f32.bf16.bf16.f32 "
        "{%0,%1,%2,%3}, {%4,%5,%6,%7}, {%8,%9}, {%0,%1,%2,%3};"
        : "+f"(c[0]), "+f"(c[1]), "+f"(c[2]), "+f"(c[3])
        : "r"(a[0]), "r"(a[1]), "r"(a[2]), "r"(a[3]), "r"(b0), "r"(b1));
}
__device__ __forceinline__ uint32_t pack_bf16x2(float lo, float hi) {
    __nv_bfloat162 p = __floats2bfloat162_rn(lo, hi);
    return *reinterpret_cast<uint32_t*>(&p);
}
__device__ __forceinline__ float rnd_bf16(float v) {
    return __bfloat162float(__float2bfloat16_rn(v));
}

// ---------------------------------------------------------------------------
// Prepass: W f32 (e4m3-exact values) -> bf16 scratch. Lossless.
__global__ void __launch_bounds__(256) convert_w_kernel(const float* __restrict__ w) {
    size_t i = ((size_t)blockIdx.x * blockDim.x + threadIdx.x) * 8;
    if (i >= (size_t)NTOT * KTOT) return;
    float4 v0 = *reinterpret_cast<const float4*>(w + i);
    float4 v1 = *reinterpret_cast<const float4*>(w + i + 4);
    uint4 o;
    o.x = pack_bf16x2(v0.x, v0.y);
    o.y = pack_bf16x2(v0.z, v0.w);
    o.z = pack_bf16x2(v1.x, v1.y);
    o.w = pack_bf16x2(v1.z, v1.w);
    *reinterpret_cast<uint4*>(g_wb + i) = o;
}

// ---------------------------------------------------------------------------
__global__ void __launch_bounds__(NTHREADS, 1) gemm_kernel(
    const float* __restrict__ x,          // f32 container of bf16 values
    const void* __restrict__ bias,        // f32 (or bf16 fallback)
    float* __restrict__ out) {            // f32 output

    extern __shared__ char smem[];
    const uint32_t sbase = smem_u32(smem);
    __shared__ int bias_is_f32;

    const int tid = threadIdx.x;
    const int wid = tid >> 5;
    const int lid = tid & 31;
    const int warp_m = wid & 3;   // 32-row slab
    const int warp_n = wid >> 2;  // 64-col slab
    const int m0 = blockIdx.y * TILE_M;
    const int n0 = blockIdx.x * TILE_N;
    const int grp = lid >> 2;     // 0..7
    const int tig = lid & 3;      // 0..3

    // Bias container detect: f32-of-bf16 has zero low halves; bf16 doesn't.
    if (tid == 0) {
        const uint32_t* bw = reinterpret_cast<const uint32_t*>(bias);
        int z = 0;
        for (int i = 0; i < 64; i++)
            if ((bw[i] & 0xFFFFu) == 0) z++;
        bias_is_f32 = (z >= 32) ? 1 : 0;
    }

    const float* aG = x + (size_t)m0 * KTOT;
    const char* bGc = reinterpret_cast<const char*>(g_wb) + (size_t)(n0)*KTOT * 2;

    // A-load coords: 4 threads/row, 16 f32 each (64B f32 -> 32B bf16)
    const int a_r = tid >> 2;            // 0..127
    const int a_c0 = (tid & 3) * 16;     // f32 col offset in chunk
    // B cp.async coords: 2 threads/row, 64B each
    const int b_r = tid >> 1;            // 0..255
    const int b_o = (tid & 1) * 64;      // byte offset in 128B row

    float acc[2][8][4];
#pragma unroll
    for (int i = 0; i < 2; i++)
#pragma unroll
        for (int j = 0; j < 8; j++)
#pragma unroll
            for (int k = 0; k < 4; k++) acc[i][j][k] = 0.f;

    float4 ar[4];  // A staging (16 f32)

#define LOAD_A(ch)                                                              \
    do {                                                                        \
        const float* s = aG + (size_t)a_r * KTOT + (ch) * KC + a_c0;            \
        ar[0] = *reinterpret_cast<const float4*>(s);                            \
        ar[1] = *reinterpret_cast<const float4*>(s + 4);                        \
        ar[2] = *reinterpret_cast<const float4*>(s + 8);                        \
        ar[3] = *reinterpret_cast<const float4*>(s + 12);                       \
    } while (0)

#define STORE_A(s)                                                              \
    do {                                                                        \
        uint32_t off = (s) * STAGE_BYTES + a_r * STRIDE + a_c0 * 2;             \
        uint4 o0, o1;                                                           \
        o0.x = pack_bf16x2(ar[0].x, ar[0].y); o0.y = pack_bf16x2(ar[0].z, ar[0].w); \
        o0.z = pack_bf16x2(ar[1].x, ar[1].y); o0.w = pack_bf16x2(ar[1].z, ar[1].w); \
        o1.x = pack_bf16x2(ar[2].x, ar[2].y); o1.y = pack_bf16x2(ar[2].z, ar[2].w); \
        o1.z = pack_bf16x2(ar[3].x, ar[3].y); o1.w = pack_bf16x2(ar[3].z, ar[3].w); \
        *reinterpret_cast<uint4*>(smem + off) = o0;                             \
        *reinterpret_cast<uint4*>(smem + off + 16) = o1;                        \
    } while (0)

#define ISSUE_B(ch, s)                                                          \
    do {                                                                        \
        uint32_t dst = sbase + (s) * STAGE_BYTES + A_BYTES + b_r * STRIDE + b_o; \
        const char* src = bGc + (size_t)b_r * (KTOT * 2) + (ch) * (KC * 2) + b_o; \
        cp_async16(dst, src);                                                   \
        cp_async16(dst + 16, src + 16);                                         \
        cp_async16(dst + 32, src + 32);                                         \
        cp_async16(dst + 48, src + 48);                                         \
        asm volatile("cp.async.commit_group;");                                 \
    } while (0)

    // ---- prologue ----
    LOAD_A(0);
    ISSUE_B(0, 0);
    STORE_A(0);
    asm volatile("cp.async.wait_group 0;" ::: "memory");
    __syncthreads();

    // Fragment offsets (validated R6 coordinates)
    const uint32_t a_off0 = (uint32_t)(warp_m * 32 + grp) * STRIDE + tig * 4;
    const uint32_t b_off0 = A_BYTES + (uint32_t)(warp_n * 64 + grp) * STRIDE + tig * 4;

    for (int ch = 0; ch < NCHUNK; ch++) {
        const int s = ch & 1;
        const bool more = (ch + 1) < NCHUNK;
        if (more) {
            LOAD_A(ch + 1);
            ISSUE_B(ch + 1, s ^ 1);
        }

        const uint32_t stg = sbase + s * STAGE_BYTES;
        const uint32_t a_base = stg + a_off0;
        const uint32_t b_base = stg + b_off0;

#pragma unroll
        for (int ks = 0; ks < 4; ks++) {
            const uint32_t kso = (uint32_t)ks * 32;
            uint32_t a[2][4];
#pragma unroll
            for (int i = 0; i < 2; i++) {
                const uint32_t ab = a_base + (uint32_t)i * 16 * STRIDE + kso;
                a[i][0] = lds32(ab);
                a[i][1] = lds32(ab + 8 * STRIDE);
                a[i][2] = lds32(ab + 16);
                a[i][3] = lds32(ab + 8 * STRIDE + 16);
            }
#pragma unroll
            for (int g8 = 0; g8 < 8; g8++) {
                const uint32_t bb = b_base + (uint32_t)g8 * 8 * STRIDE + kso;
                const uint32_t b0 = lds32(bb);
                const uint32_t b1 = lds32(bb + 16);
                mma_bf16(acc[0][g8], a[0], b0, b1);
                mma_bf16(acc[1][g8], a[1], b0, b1);
            }
        }

        if (more) {
            asm volatile("cp.async.wait_group 0;" ::: "memory");
            STORE_A(s ^ 1);
        }
        __syncthreads();
    }

    // ---- epilogue: replicate ref rounding: bf16(bf16(acc) + bias), store f32
    const int col0 = n0 + warp_n * 64 + tig * 2;
    const int row0 = m0 + warp_m * 32 + grp;
    const int bf32 = bias_is_f32;
#pragma unroll
    for (int g8 = 0; g8 < 8; g8++) {
        const int col = col0 + g8 * 8;
        float bv0, bv1;
        if (bf32) {
            bv0 = reinterpret_cast<const float*>(bias)[col];
            bv1 = reinterpret_cast<const float*>(bias)[col + 1];
        } else {
            bv0 = __bfloat162float(reinterpret_cast<const __nv_bfloat16*>(bias)[col]);
            bv1 = __bfloat162float(reinterpret_cast<const __nv_bfloat16*>(bias)[col + 1]);
        }
#pragma unroll
        for (int i = 0; i < 2; i++) {
            const int r = row0 + i * 16;
            float o0 = rnd_bf16(rnd_bf16(acc[i][g8][0]) + bv0);
            float o1 = rnd_bf16(rnd_bf16(acc[i][g8][1]) + bv1);
            float o2 = rnd_bf16(rnd_bf16(acc[i][g8][2]) + bv0);
            float o3 = rnd_bf16(rnd_bf16(acc[i][g8][3]) + bv1);
            float2* d0 = reinterpret_cast<float2*>(out + (size_t)r * NTOT + col);
            float2* d1 = reinterpret_cast<float2*>(out + (size_t)(r + 8) * NTOT + col);
            d0[0] = make_float2(o0, o1);
            d1[0] = make_float2(o2, o3);
        }
    }
#undef LOAD_A
#undef STORE_A
#undef ISSUE_B
}

// ---------------------------------------------------------------------------
extern "C" void kernel_launch(void* const* d_in, const int* in_sizes, int n_in,
                              void* d_out, int out_size) {
    // Size-keyed input identification (order-proof; validated by probe).
    const void* px = nullptr;
    const void* pw = nullptr;
    const void* pb = nullptr;
    for (int i = 0; i < n_in; i++) {
        if (in_sizes[i] == MTOT * KTOT)      px = d_in[i];
        else if (in_sizes[i] == NTOT * KTOT) pw = d_in[i];
        else if (in_sizes[i] == NTOT)        pb = d_in[i];
    }
    if (!px) px = d_in[0];
    if (!pw) pw = d_in[1];
    if (!pb) pb = d_in[2];

    cudaFuncSetAttribute(gemm_kernel, cudaFuncAttributeMaxDynamicSharedMemorySize,
                         SMEM_BYTES);

    const size_t total = (size_t)NTOT * KTOT;
    convert_w_kernel<<<(int)((total / 8 + 255) / 256), 256>>>((const float*)pw);

    dim3 grid(NTOT / TILE_N, MTOT / TILE_M);  // (12, 64)
    gemm_kernel<<<grid, NTHREADS, SMEM_BYTES>>>(
        (const float*)px, pb, (float*)d_out);
}

// round 15
// speedup vs baseline: 1.0991x; 1.0991x over previous
#include <cuda_runtime.h>
#include <cuda_bf16.h>
#include <cstdint>

// y[M,N] = x[M,K] @ W[N,K]^T + bias[N].  M=8192, N=K=3072.
// Ground truth (R13 probe, R14 pass): all buffers f32 containers.
//   x: f32 of bf16-exact values; W: f32 of e4m3-exact; bias f32; out f32,
//   reference rounding = f32(bf16(bf16(acc) + bias)).
// R15: prepass-convert BOTH x and W to bf16 scratch; mainloop = cp.async for
// A and B + ldmatrix fragments (R3-validated lane plumbing) + mma.sync bf16.

#define MTOT 8192
#define NTOT 3072
#define KTOT 3072

#define TILE_M 128
#define TILE_N 256
#define KC 64
#define NCHUNK (KTOT / KC)       // 48
#define NTHREADS 512

#define STRIDE 144               // smem row stride bytes (128B data + 16B pad)
#define A_BYTES (TILE_M * STRIDE)            // 18432
#define B_BYTES (TILE_N * STRIDE)            // 36864
#define STAGE_BYTES (A_BYTES + B_BYTES)      // 55296
#define SMEM_BYTES (2 * STAGE_BYTES)         // 110592

// bf16 scratch (allocation-free rule: __device__ globals)
__device__ __align__(16) __nv_bfloat16 g_wb[(size_t)NTOT * KTOT];   // 18.9 MB
__device__ __align__(16) __nv_bfloat16 g_xb[(size_t)MTOT * KTOT];   // 50.3 MB

// ---------------------------------------------------------------------------
__device__ __forceinline__ uint32_t smem_u32(const void* p) {
    uint32_t a;
    asm("{ .reg .u64 t; cvta.to.shared.u64 t, %1; cvt.u32.u64 %0, t; }"
        : "=r"(a) : "l"(p));
    return a;
}
__device__ __forceinline__ void cp_async16(uint32_t saddr, const void* gaddr) {
    asm volatile("cp.async.cg.shared.global [%0], [%1], 16;"
                 :: "r"(saddr), "l"(gaddr));
}
__device__ __forceinline__ void ldsm_x4(uint32_t (&r)[4], uint32_t addr) {
    asm volatile("ldmatrix.sync.aligned.m8n8.x4.shared.b16 {%0,%1,%2,%3}, [%4];"
                 : "=r"(r[0]), "=r"(r[1]), "=r"(r[2]), "=r"(r[3]) : "r"(addr));
}
__device__ __forceinline__ void mma_bf16(float (&c)[4], const uint32_t (&a)[4],
                                         uint32_t b0, uint32_t b1) {
    asm volatile(
        "mma.sync.aligned.m16n8k16.row.col.f32.bf16.bf16.f32 "
        "{%0,%1,%2,%3}, {%4,%5,%6,%7}, {%8,%9}, {%0,%1,%2,%3};"
        : "+f"(c[0]), "+f"(c[1]), "+f"(c[2]), "+f"(c[3])
        : "r"(a[0]), "r"(a[1]), "r"(a[2]), "r"(a[3]), "r"(b0), "r"(b1));
}
__device__ __forceinline__ uint32_t pack_bf16x2(float lo, float hi) {
    __nv_bfloat162 p = __floats2bfloat162_rn(lo, hi);
    return *reinterpret_cast<uint32_t*>(&p);
}
__device__ __forceinline__ float rnd_bf16(float v) {
    return __bfloat162float(__float2bfloat16_rn(v));
}

// ---------------------------------------------------------------------------
// Prepass: f32 -> bf16 (lossless for bf16-exact / e4m3-exact values).
__global__ void __launch_bounds__(256) convert_kernel(
    const float* __restrict__ src, __nv_bfloat16* __restrict__ dst, size_t n) {
    size_t i = ((size_t)blockIdx.x * blockDim.x + threadIdx.x) * 8;
    if (i >= n) return;
    float4 v0 = *reinterpret_cast<const float4*>(src + i);
    float4 v1 = *reinterpret_cast<const float4*>(src + i + 4);
    uint4 o;
    o.x = pack_bf16x2(v0.x, v0.y);
    o.y = pack_bf16x2(v0.z, v0.w);
    o.z = pack_bf16x2(v1.x, v1.y);
    o.w = pack_bf16x2(v1.z, v1.w);
    *reinterpret_cast<uint4*>(dst + i) = o;
}

// ---------------------------------------------------------------------------
__global__ void __launch_bounds__(NTHREADS, 1) gemm_kernel(
    const void* __restrict__ bias,        // f32 (bf16 fallback via detect)
    float* __restrict__ out) {

    extern __shared__ char smem[];
    const uint32_t sbase = smem_u32(smem);
    __shared__ int bias_is_f32;

    const int tid = threadIdx.x;
    const int wid = tid >> 5;
    const int lid = tid & 31;
    const int warp_m = wid & 3;   // 32-row slab
    const int warp_n = wid >> 2;  // 64-col slab
    const int m0 = blockIdx.y * TILE_M;
    const int n0 = blockIdx.x * TILE_N;
    const int grp = lid >> 2;
    const int tig = lid & 3;

    if (tid == 0) {
        const uint32_t* bw = reinterpret_cast<const uint32_t*>(bias);
        int z = 0;
        for (int i = 0; i < 64; i++)
            if ((bw[i] & 0xFFFFu) == 0) z++;
        bias_is_f32 = (z >= 32) ? 1 : 0;
    }

    const char* aG = reinterpret_cast<const char*>(g_xb) + (size_t)m0 * KTOT * 2;
    const char* bG = reinterpret_cast<const char*>(g_wb) + (size_t)n0 * KTOT * 2;

    // cp.async coords: A 4 thr/row x 32B; B 2 thr/row x 64B
    const int a_r = tid >> 2, a_o = (tid & 3) * 32;
    const int b_r = tid >> 1, b_o = (tid & 1) * 64;

    float acc[2][8][4];
#pragma unroll
    for (int i = 0; i < 2; i++)
#pragma unroll
        for (int j = 0; j < 8; j++)
#pragma unroll
            for (int k = 0; k < 4; k++) acc[i][j][k] = 0.f;

#define ISSUE(ch, s)                                                            \
    do {                                                                        \
        uint32_t dstA = sbase + (s) * STAGE_BYTES + a_r * STRIDE + a_o;         \
        const char* srcA = aG + (size_t)a_r * (KTOT * 2) + (ch) * (KC * 2) + a_o; \
        cp_async16(dstA, srcA);                                                 \
        cp_async16(dstA + 16, srcA + 16);                                       \
        uint32_t dstB = sbase + (s) * STAGE_BYTES + A_BYTES + b_r * STRIDE + b_o; \
        const char* srcB = bG + (size_t)b_r * (KTOT * 2) + (ch) * (KC * 2) + b_o; \
        cp_async16(dstB, srcB);                                                 \
        cp_async16(dstB + 16, srcB + 16);                                       \
        cp_async16(dstB + 32, srcB + 32);                                       \
        cp_async16(dstB + 48, srcB + 48);                                       \
        asm volatile("cp.async.commit_group;");                                 \
    } while (0)

    // ---- prologue ----
    ISSUE(0, 0);
    asm volatile("cp.async.wait_group 0;" ::: "memory");
    __syncthreads();

    // ldmatrix fragment offsets (R3-validated lane plumbing)
    const uint32_t a_frag_off =
        (uint32_t)(warp_m * 32 + (lid & 15)) * STRIDE + (lid >> 4) * 16;
    const uint32_t b_frag_off =
        A_BYTES + (uint32_t)(warp_n * 64 + ((lid >> 4) << 3) + (lid & 7)) * STRIDE +
        ((lid >> 3) & 1) * 16;

    for (int ch = 0; ch < NCHUNK; ch++) {
        const int s = ch & 1;
        const bool more = (ch + 1) < NCHUNK;
        if (more) ISSUE(ch + 1, s ^ 1);

        const uint32_t stg = sbase + s * STAGE_BYTES;
        const uint32_t a_base = stg + a_frag_off;
        const uint32_t b_base = stg + b_frag_off;

#pragma unroll
        for (int ks = 0; ks < 4; ks++) {
            const uint32_t kso = (uint32_t)ks * 32;
            uint32_t a[2][4];
            ldsm_x4(a[0], a_base + kso);
            ldsm_x4(a[1], a_base + 16 * STRIDE + kso);
            uint32_t b[4][4];
#pragma unroll
            for (int jn = 0; jn < 4; jn++)
                ldsm_x4(b[jn], b_base + (uint32_t)jn * 16 * STRIDE + kso);
#pragma unroll
            for (int i = 0; i < 2; i++)
#pragma unroll
                for (int tn = 0; tn < 8; tn++) {
                    const int jn = tn >> 1;
                    if (tn & 1) mma_bf16(acc[i][tn], a[i], b[jn][2], b[jn][3]);
                    else        mma_bf16(acc[i][tn], a[i], b[jn][0], b[jn][1]);
                }
        }

        if (more) asm volatile("cp.async.wait_group 0;" ::: "memory");
        __syncthreads();
    }

    // ---- epilogue: f32(bf16(bf16(acc) + bias)) ----
    const int col0 = n0 + warp_n * 64 + tig * 2;
    const int row0 = m0 + warp_m * 32 + grp;
    const int bf32 = bias_is_f32;
#pragma unroll
    for (int tn = 0; tn < 8; tn++) {
        const int col = col0 + tn * 8;
        float bv0, bv1;
        if (bf32) {
            bv0 = reinterpret_cast<const float*>(bias)[col];
            bv1 = reinterpret_cast<const float*>(bias)[col + 1];
        } else {
            bv0 = __bfloat162float(reinterpret_cast<const __nv_bfloat16*>(bias)[col]);
            bv1 = __bfloat162float(reinterpret_cast<const __nv_bfloat16*>(bias)[col + 1]);
        }
#pragma unroll
        for (int i = 0; i < 2; i++) {
            const int r = row0 + i * 16;
            float o0 = rnd_bf16(rnd_bf16(acc[i][tn][0]) + bv0);
            float o1 = rnd_bf16(rnd_bf16(acc[i][tn][1]) + bv1);
            float o2 = rnd_bf16(rnd_bf16(acc[i][tn][2]) + bv0);
            float o3 = rnd_bf16(rnd_bf16(acc[i][tn][3]) + bv1);
            *reinterpret_cast<float2*>(out + (size_t)r * NTOT + col) =
                make_float2(o0, o1);
            *reinterpret_cast<float2*>(out + (size_t)(r + 8) * NTOT + col) =
                make_float2(o2, o3);
        }
    }
#undef ISSUE
}

// ---------------------------------------------------------------------------
extern "C" void kernel_launch(void* const* d_in, const int* in_sizes, int n_in,
                              void* d_out, int out_size) {
    const void* px = nullptr;
    const void* pw = nullptr;
    const void* pb = nullptr;
    for (int i = 0; i < n_in; i++) {
        if (in_sizes[i] == MTOT * KTOT)      px = d_in[i];
        else if (in_sizes[i] == NTOT * KTOT) pw = d_in[i];
        else if (in_sizes[i] == NTOT)        pb = d_in[i];
    }
    if (!px) px = d_in[0];
    if (!pw) pw = d_in[1];
    if (!pb) pb = d_in[2];

    cudaFuncSetAttribute(gemm_kernel, cudaFuncAttributeMaxDynamicSharedMemorySize,
                         SMEM_BYTES);

    // Prepasses: f32 -> bf16 scratch for W and x.
    __nv_bfloat16* wb_ptr;  cudaGetSymbolAddress((void**)&wb_ptr, g_wb);
    __nv_bfloat16* xb_ptr;  cudaGetSymbolAddress((void**)&xb_ptr, g_xb);
    const size_t wN = (size_t)NTOT * KTOT;
    const size_t xN = (size_t)MTOT * KTOT;
    convert_kernel<<<(int)((wN / 8 + 255) / 256), 256>>>((const float*)pw, wb_ptr, wN);
    convert_kernel<<<(int)((xN / 8 + 255) / 256), 256>>>((const float*)px, xb_ptr, xN);

    dim3 grid(NTOT / TILE_N, MTOT / TILE_M);  // (12, 64)
    gemm_kernel<<<grid, NTHREADS, SMEM_BYTES>>>(pb, (float*)d_out);
}

// round 16
// speedup vs baseline: 1.1267x; 1.0251x over previous
#include <cuda_runtime.h>
#include <cuda_bf16.h>
#include <cstdint>

// y[M,N] = x[M,K] @ W[N,K]^T + bias[N].  M=8192, N=K=3072.
// All I/O buffers are f32 containers (probe-verified):
//   x: f32 of bf16-exact; W: f32 of e4m3-exact; bias f32; out f32 with
//   reference rounding f32(bf16(bf16(acc)+bias)).
// R16: 128x128 tile, 256 threads, double buffer, 2 CTAs/SM for latency hiding.

#define MTOT 8192
#define NTOT 3072
#define KTOT 3072

#define TILE_M 128
#define TILE_N 128
#define KC 64
#define NCHUNK (KTOT / KC)       // 48
#define NTHREADS 256

#define STRIDE 144               // 128B data + 16B pad
#define A_BYTES (TILE_M * STRIDE)            // 18432
#define B_BYTES (TILE_N * STRIDE)            // 18432
#define STAGE_BYTES (A_BYTES + B_BYTES)      // 36864
#define SMEM_BYTES (2 * STAGE_BYTES)         // 73728 -> 2 CTAs/SM

__device__ __align__(16) __nv_bfloat16 g_wb[(size_t)NTOT * KTOT];   // 18.9 MB
__device__ __align__(16) __nv_bfloat16 g_xb[(size_t)MTOT * KTOT];   // 50.3 MB

// ---------------------------------------------------------------------------
__device__ __forceinline__ uint32_t smem_u32(const void* p) {
    uint32_t a;
    asm("{ .reg .u64 t; cvta.to.shared.u64 t, %1; cvt.u32.u64 %0, t; }"
        : "=r"(a) : "l"(p));
    return a;
}
__device__ __forceinline__ void cp_async16(uint32_t saddr, const void* gaddr) {
    asm volatile("cp.async.cg.shared.global [%0], [%1], 16;"
                 :: "r"(saddr), "l"(gaddr));
}
__device__ __forceinline__ void ldsm_x4(uint32_t (&r)[4], uint32_t addr) {
    asm volatile("ldmatrix.sync.aligned.m8n8.x4.shared.b16 {%0,%1,%2,%3}, [%4];"
                 : "=r"(r[0]), "=r"(r[1]), "=r"(r[2]), "=r"(r[3]) : "r"(addr));
}
__device__ __forceinline__ void mma_bf16(float (&c)[4], const uint32_t (&a)[4],
                                         uint32_t b0, uint32_t b1) {
    asm volatile(
        "mma.sync.aligned.m16n8k16.row.col.f32.bf16.bf16.f32 "
        "{%0,%1,%2,%3}, {%4,%5,%6,%7}, {%8,%9}, {%0,%1,%2,%3};"
        : "+f"(c[0]), "+f"(c[1]), "+f"(c[2]), "+f"(c[3])
        : "r"(a[0]), "r"(a[1]), "r"(a[2]), "r"(a[3]), "r"(b0), "r"(b1));
}
__device__ __forceinline__ uint32_t pack_bf16x2(float lo, float hi) {
    __nv_bfloat162 p = __floats2bfloat162_rn(lo, hi);
    return *reinterpret_cast<uint32_t*>(&p);
}
__device__ __forceinline__ float rnd_bf16(float v) {
    return __bfloat162float(__float2bfloat16_rn(v));
}

// ---------------------------------------------------------------------------
__global__ void __launch_bounds__(256) convert_kernel(
    const float* __restrict__ src, __nv_bfloat16* __restrict__ dst, size_t n) {
    size_t i = ((size_t)blockIdx.x * blockDim.x + threadIdx.x) * 8;
    if (i >= n) return;
    float4 v0 = *reinterpret_cast<const float4*>(src + i);
    float4 v1 = *reinterpret_cast<const float4*>(src + i + 4);
    uint4 o;
    o.x = pack_bf16x2(v0.x, v0.y);
    o.y = pack_bf16x2(v0.z, v0.w);
    o.z = pack_bf16x2(v1.x, v1.y);
    o.w = pack_bf16x2(v1.z, v1.w);
    *reinterpret_cast<uint4*>(dst + i) = o;
}

// ---------------------------------------------------------------------------
__global__ void __launch_bounds__(NTHREADS, 2) gemm_kernel(
    const void* __restrict__ bias,
    float* __restrict__ out) {

    extern __shared__ char smem[];
    const uint32_t sbase = smem_u32(smem);
    __shared__ int bias_is_f32;

    const int tid = threadIdx.x;
    const int wid = tid >> 5;
    const int lid = tid & 31;
    const int warp_m = wid & 3;   // 0..3 -> 32-row slab
    const int warp_n = wid >> 2;  // 0..1 -> 64-col slab
    const int m0 = blockIdx.y * TILE_M;
    const int n0 = blockIdx.x * TILE_N;
    const int grp = lid >> 2;
    const int tig = lid & 3;

    if (tid == 0) {
        const uint32_t* bw = reinterpret_cast<const uint32_t*>(bias);
        int z = 0;
        for (int i = 0; i < 64; i++)
            if ((bw[i] & 0xFFFFu) == 0) z++;
        bias_is_f32 = (z >= 32) ? 1 : 0;
    }

    const char* aG = reinterpret_cast<const char*>(g_xb) + (size_t)m0 * KTOT * 2;
    const char* bG = reinterpret_cast<const char*>(g_wb) + (size_t)n0 * KTOT * 2;

    // cp.async coords: 2 threads per 128B row (64B each), rows 0..127
    const int l_r = tid >> 1, l_o = (tid & 1) * 64;

    float acc[2][8][4];
#pragma unroll
    for (int i = 0; i < 2; i++)
#pragma unroll
        for (int j = 0; j < 8; j++)
#pragma unroll
            for (int k = 0; k < 4; k++) acc[i][j][k] = 0.f;

#define ISSUE(ch, s)                                                            \
    do {                                                                        \
        uint32_t dstA = sbase + (s) * STAGE_BYTES + l_r * STRIDE + l_o;         \
        const char* srcA = aG + (size_t)l_r * (KTOT * 2) + (ch) * (KC * 2) + l_o; \
        cp_async16(dstA, srcA);                                                 \
        cp_async16(dstA + 16, srcA + 16);                                       \
        cp_async16(dstA + 32, srcA + 32);                                       \
        cp_async16(dstA + 48, srcA + 48);                                       \
        uint32_t dstB = sbase + (s) * STAGE_BYTES + A_BYTES + l_r * STRIDE + l_o; \
        const char* srcB = bG + (size_t)l_r * (KTOT * 2) + (ch) * (KC * 2) + l_o; \
        cp_async16(dstB, srcB);                                                 \
        cp_async16(dstB + 16, srcB + 16);                                       \
        cp_async16(dstB + 32, srcB + 32);                                       \
        cp_async16(dstB + 48, srcB + 48);                                       \
        asm volatile("cp.async.commit_group;");                                 \
    } while (0)

    // ---- prologue ----
    ISSUE(0, 0);
    asm volatile("cp.async.wait_group 0;" ::: "memory");
    __syncthreads();

    // ldmatrix fragment offsets (R3/R15-validated lane plumbing)
    const uint32_t a_frag_off =
        (uint32_t)(warp_m * 32 + (lid & 15)) * STRIDE + (lid >> 4) * 16;
    const uint32_t b_frag_off =
        A_BYTES + (uint32_t)(warp_n * 64 + ((lid >> 4) << 3) + (lid & 7)) * STRIDE +
        ((lid >> 3) & 1) * 16;

    for (int ch = 0; ch < NCHUNK; ch++) {
        const int s = ch & 1;
        const bool more = (ch + 1) < NCHUNK;
        if (more) ISSUE(ch + 1, s ^ 1);

        const uint32_t stg = sbase + s * STAGE_BYTES;
        const uint32_t a_base = stg + a_frag_off;
        const uint32_t b_base = stg + b_frag_off;

#pragma unroll
        for (int ks = 0; ks < 4; ks++) {
            const uint32_t kso = (uint32_t)ks * 32;
            uint32_t a[2][4];
            ldsm_x4(a[0], a_base + kso);
            ldsm_x4(a[1], a_base + 16 * STRIDE + kso);
            uint32_t b[4][4];
#pragma unroll
            for (int jn = 0; jn < 4; jn++)
                ldsm_x4(b[jn], b_base + (uint32_t)jn * 16 * STRIDE + kso);
#pragma unroll
            for (int i = 0; i < 2; i++)
#pragma unroll
                for (int tn = 0; tn < 8; tn++) {
                    const int jn = tn >> 1;
                    if (tn & 1) mma_bf16(acc[i][tn], a[i], b[jn][2], b[jn][3]);
                    else        mma_bf16(acc[i][tn], a[i], b[jn][0], b[jn][1]);
                }
        }

        if (more) asm volatile("cp.async.wait_group 0;" ::: "memory");
        __syncthreads();
    }

    // ---- epilogue: f32(bf16(bf16(acc) + bias)) ----
    const int col0 = n0 + warp_n * 64 + tig * 2;
    const int row0 = m0 + warp_m * 32 + grp;
    const int bf32 = bias_is_f32;
#pragma unroll
    for (int tn = 0; tn < 8; tn++) {
        const int col = col0 + tn * 8;
        float bv0, bv1;
        if (bf32) {
            bv0 = reinterpret_cast<const float*>(bias)[col];
            bv1 = reinterpret_cast<const float*>(bias)[col + 1];
        } else {
            bv0 = __bfloat162float(reinterpret_cast<const __nv_bfloat16*>(bias)[col]);
            bv1 = __bfloat162float(reinterpret_cast<const __nv_bfloat16*>(bias)[col + 1]);
        }
#pragma unroll
        for (int i = 0; i < 2; i++) {
            const int r = row0 + i * 16;
            float o0 = rnd_bf16(rnd_bf16(acc[i][tn][0]) + bv0);
            float o1 = rnd_bf16(rnd_bf16(acc[i][tn][1]) + bv1);
            float o2 = rnd_bf16(rnd_bf16(acc[i][tn][2]) + bv0);
            float o3 = rnd_bf16(rnd_bf16(acc[i][tn][3]) + bv1);
            *reinterpret_cast<float2*>(out + (size_t)r * NTOT + col) =
                make_float2(o0, o1);
            *reinterpret_cast<float2*>(out + (size_t)(r + 8) * NTOT + col) =
                make_float2(o2, o3);
        }
    }
#undef ISSUE
}

// ---------------------------------------------------------------------------
extern "C" void kernel_launch(void* const* d_in, const int* in_sizes, int n_in,
                              void* d_out, int out_size) {
    const void* px = nullptr;
    const void* pw = nullptr;
    const void* pb = nullptr;
    for (int i = 0; i < n_in; i++) {
        if (in_sizes[i] == MTOT * KTOT)      px = d_in[i];
        else if (in_sizes[i] == NTOT * KTOT) pw = d_in[i];
        else if (in_sizes[i] == NTOT)        pb = d_in[i];
    }
    if (!px) px = d_in[0];
    if (!pw) pw = d_in[1];
    if (!pb) pb = d_in[2];

    cudaFuncSetAttribute(gemm_kernel, cudaFuncAttributeMaxDynamicSharedMemorySize,
                         SMEM_BYTES);

    __nv_bfloat16* wb_ptr;  cudaGetSymbolAddress((void**)&wb_ptr, g_wb);
    __nv_bfloat16* xb_ptr;  cudaGetSymbolAddress((void**)&xb_ptr, g_xb);
    const size_t wN = (size_t)NTOT * KTOT;
    const size_t xN = (size_t)MTOT * KTOT;
    convert_kernel<<<(int)((wN / 8 + 255) / 256), 256>>>((const float*)pw, wb_ptr, wN);
    convert_kernel<<<(int)((xN / 8 + 255) / 256), 256>>>((const float*)px, xb_ptr, xN);

    dim3 grid(NTOT / TILE_N, MTOT / TILE_M);  // (24, 64) = 1536 CTAs
    gemm_kernel<<<grid, NTHREADS, SMEM_BYTES>>>(pb, (float*)d_out);
}